// round 15
// baseline (speedup 1.0000x reference)
#include <cuda_runtime.h>
#include <math.h>
#include <stdint.h>

// ---------------------------------------------------------------------------
// Problem constants
// ---------------------------------------------------------------------------
#define NLYR   6
#define BSZ_   4
#define QLEN_  512
#define KLEN_  1024
#define DMOD   1024
#define NHEAD  16
#define DHEAD  64
#define DINNER 4096
#define VOCAB  32000
#define NROWS  (BSZ_ * QLEN_)      /* 2048 */
#define NCROWS (BSZ_ * KLEN_)      /* 4096 */

// ---------------------------------------------------------------------------
// Scratch (static device globals — allocation-free)
// ---------------------------------------------------------------------------
__device__ float g_x    [NROWS  * DMOD];
__device__ float g_xcat [NCROWS * DMOD];
__device__ float g_q    [NROWS  * DMOD];
__device__ float g_kv   [NCROWS * 2 * DMOD];
__device__ float g_rk   [KLEN_  * DMOD];
__device__ float g_pos  [KLEN_  * DMOD];
__device__ float g_vec  [NROWS  * DMOD];
__device__ float g_tmp  [NROWS  * DMOD];
__device__ float g_ffh  [NROWS  * DINNER];
__device__ float g_lgt  [(size_t)NROWS * VOCAB];

// ---------------------------------------------------------------------------
// Small helpers
// ---------------------------------------------------------------------------
__device__ __forceinline__ uint32_t pack_bf2(float lo, float hi) {
    uint32_t u;
    asm("cvt.rn.bf16x2.f32 %0, %1, %2;" : "=r"(u) : "f"(hi), "f"(lo));
    return u;
}

__device__ __forceinline__ void mma16(float* d, const uint32_t* a, const uint32_t* b) {
    asm volatile(
        "mma.sync.aligned.m16n8k16.row.col.f32.bf16.bf16.f32 "
        "{%0,%1,%2,%3}, {%4,%5,%6,%7}, {%8,%9}, {%0,%1,%2,%3};\n"
        : "+f"(d[0]), "+f"(d[1]), "+f"(d[2]), "+f"(d[3])
        : "r"(a[0]), "r"(a[1]), "r"(a[2]), "r"(a[3]), "r"(b[0]), "r"(b[1]));
}

// ---------------------------------------------------------------------------
// Embedding gather
// ---------------------------------------------------------------------------
__global__ __launch_bounds__(256) void embed_kernel(
    const int* __restrict__ data, const float* __restrict__ emb,
    float* __restrict__ x)
{
    int row = blockIdx.x;
    int tok = data[row];
    const float4* src = (const float4*)(emb + (size_t)tok * DMOD);
    float4*       dst = (float4*)(x + (size_t)row * DMOD);
    dst[threadIdx.x] = src[threadIdx.x];
}

// ---------------------------------------------------------------------------
// Positional embedding
// ---------------------------------------------------------------------------
__global__ __launch_bounds__(512) void posemb_kernel(float* __restrict__ pos)
{
    int p = blockIdx.x;
    int f = threadIdx.x;
    double invf = exp(-((double)(2 * f) / 1024.0) * log(10000.0));
    float ang = (float)((double)(KLEN_ - 1 - p) * invf);
    pos[(size_t)p * DMOD + f]       = sinf(ang);
    pos[(size_t)p * DMOD + 512 + f] = cosf(ang);
}

// ---------------------------------------------------------------------------
// Concat [mem ; x]
// ---------------------------------------------------------------------------
__global__ __launch_bounds__(256) void concat_kernel(
    const float* __restrict__ mem, const float* __restrict__ x,
    float* __restrict__ xc)
{
    int row = blockIdx.x;
    int b = row >> 10, j = row & 1023;
    const float4* src = (j < QLEN_)
        ? (const float4*)(mem + ((size_t)b * QLEN_ + j) * DMOD)
        : (const float4*)(x   + ((size_t)b * QLEN_ + (j - QLEN_)) * DMOD);
    float4* dst = (float4*)(xc + (size_t)row * DMOD);
    dst[threadIdx.x] = src[threadIdx.x];
}

// ---------------------------------------------------------------------------
// BF16 tensor-core GEMM (fp32 in/out, bf16 compute, fp32 accumulate).
//   C[M,N] = A[M,K] @ B     (BT=false: B is [K,N];  BT=true: B is [N,K], C=A@B^T)
// Block tile 128x128x32, 256 threads = 8 warps (2m x 4n), warp tile 64x32,
// mma.m16n8k16. 2 CTAs/SM: cross-CTA overlap hides gmem+scatter latency, so
// no per-warp register prefetch (keeps regs <= 128 for occupancy 2).
// Fragment smem layouts identical to R13 (validated):
//   A: per (16-row tile mtg, k16-step ks) segment, lane^(seg&7) holds uint4.
//   B: per (8-col tile ntg, k16-step ks) segment, lane^(ntg&15) holds uint2.
// Requires M%128==0, N%128==0, K%32==0. EPI: 0=none, 1=+bias, 2=relu(+bias)
// ---------------------------------------------------------------------------
template<int EPI, bool BT>
__global__ __launch_bounds__(256, 2) void gemm_bf16(
    const float* __restrict__ A, const float* __restrict__ Bm,
    const float* __restrict__ bias, float* __restrict__ C,
    int M, int N, int K)
{
    __shared__ __align__(16) uint32_t As[2048];   // 8 KB
    __shared__ __align__(16) uint32_t Bs[2048];   // 8 KB

    const int tid  = threadIdx.x;
    const int lane = tid & 31;
    const int wid  = tid >> 5;
    const int wm   = wid >> 2;          // 0..1
    const int wn   = wid & 3;           // 0..3
    const int bm   = blockIdx.y << 7;
    const int bn   = blockIdx.x << 7;

    // ---- A loader: row = tid>>1 (128 rows), 16 k at (tid&1)*16 -----------
    const int arow = tid >> 1;
    const float* Ap = A + (size_t)(bm + arow) * K + ((tid & 1) << 4);

    // ---- B loader ---------------------------------------------------------
    const float* Bp;
    if (BT) {
        Bp = Bm + (size_t)(bn + (tid >> 1)) * K + ((tid & 1) << 4);
    } else {
        Bp = Bm + (size_t)((tid >> 4) << 1) * N + bn + ((tid & 15) << 3);
    }

    float acc[4][4][4];
#pragma unroll
    for (int mt = 0; mt < 4; mt++)
#pragma unroll
        for (int nt = 0; nt < 4; nt++)
#pragma unroll
            for (int r = 0; r < 4; r++) acc[mt][nt][r] = 0.f;

    const int nk = K >> 5;

    for (int kt = 0; kt < nk; kt++) {
        // ---- load this ktile from gmem ---------------------------------
        float4 ra[4], rb[4];
        {
            const float* Ap2 = Ap + (size_t)kt * 32;
#pragma unroll
            for (int u = 0; u < 4; u++) ra[u] = ((const float4*)Ap2)[u];
            if (BT) {
                const float* Bp2 = Bp + (size_t)kt * 32;
#pragma unroll
                for (int u = 0; u < 4; u++) rb[u] = ((const float4*)Bp2)[u];
            } else {
                const float* Bp2 = Bp + (size_t)kt * 32 * N;
                rb[0] = ((const float4*)Bp2)[0];
                rb[1] = ((const float4*)Bp2)[1];
                rb[2] = ((const float4*)(Bp2 + N))[0];
                rb[3] = ((const float4*)(Bp2 + N))[1];
            }
        }

        // ---- scatter A into bf16 fragment layout ------------------------
        {
            const int mtg = arow >> 4, r16 = arow & 15;
            const int g = r16 & 7, hb = r16 >> 3;
            const int seg = (mtg << 1) + (tid & 1);
            const int v = seg & 7;
            float vv[16] = {ra[0].x, ra[0].y, ra[0].z, ra[0].w,
                            ra[1].x, ra[1].y, ra[1].z, ra[1].w,
                            ra[2].x, ra[2].y, ra[2].z, ra[2].w,
                            ra[3].x, ra[3].y, ra[3].z, ra[3].w};
#pragma unroll
            for (int p = 0; p < 8; p++) {
                int t = p & 3, kh = p >> 2;
                int ls = ((g << 2) + t) ^ v;
                As[(((seg << 5) + ls) << 2) + hb + (kh << 1)] =
                    pack_bf2(vv[2 * p], vv[2 * p + 1]);
            }
        }
        // ---- scatter B ----------------------------------------------------
        if (BT) {
            const int n = tid >> 1;
            const int g = n & 7, ntg = n >> 3;
            const int ks = tid & 1;
            const int segB = (ntg << 1) + ks;
            const int v = ntg & 15;
            float vv[16] = {rb[0].x, rb[0].y, rb[0].z, rb[0].w,
                            rb[1].x, rb[1].y, rb[1].z, rb[1].w,
                            rb[2].x, rb[2].y, rb[2].z, rb[2].w,
                            rb[3].x, rb[3].y, rb[3].z, rb[3].w};
#pragma unroll
            for (int p = 0; p < 8; p++) {
                int t = p & 3, breg = p >> 2;
                int ls = ((g << 2) + t) ^ v;
                Bs[(((segB << 5) + ls) << 1) + breg] =
                    pack_bf2(vv[2 * p], vv[2 * p + 1]);
            }
        } else {
            const int kp = tid >> 4;
            const int cg = tid & 15;
            const int ks = kp >> 3, t = kp & 3, breg = (kp >> 2) & 1;
            const int segB = (cg << 1) + ks;
            const int v = cg & 15;
            float r0[8] = {rb[0].x, rb[0].y, rb[0].z, rb[0].w,
                           rb[1].x, rb[1].y, rb[1].z, rb[1].w};
            float r1[8] = {rb[2].x, rb[2].y, rb[2].z, rb[2].w,
                           rb[3].x, rb[3].y, rb[3].z, rb[3].w};
#pragma unroll
            for (int j = 0; j < 8; j++) {
                int ls = ((j << 2) + t) ^ v;
                Bs[(((segB << 5) + ls) << 1) + breg] = pack_bf2(r0[j], r1[j]);
            }
        }
        __syncthreads();

        // ---- compute --------------------------------------------------------
#pragma unroll
        for (int ks = 0; ks < 2; ks++) {
            uint4 af[4];
            uint2 bf[4];
#pragma unroll
            for (int mt = 0; mt < 4; mt++) {
                int seg = (((wm << 2) + mt) << 1) + ks;
                af[mt] = ((const uint4*)As)[(seg << 5) + (lane ^ (seg & 7))];
            }
#pragma unroll
            for (int nt = 0; nt < 4; nt++) {
                int ntg = (wn << 2) + nt;
                int segB = (ntg << 1) + ks;
                bf[nt] = ((const uint2*)Bs)[(segB << 5) + (lane ^ (ntg & 15))];
            }
#pragma unroll
            for (int mt = 0; mt < 4; mt++)
#pragma unroll
                for (int nt = 0; nt < 4; nt++)
                    mma16(acc[mt][nt], (const uint32_t*)&af[mt],
                          (const uint32_t*)&bf[nt]);
        }
        __syncthreads();
    }

    // ---- epilogue -----------------------------------------------------------
    const int g  = lane >> 2;
    const int t2 = (lane & 3) << 1;
#pragma unroll
    for (int mt = 0; mt < 4; mt++) {
        int row = bm + wm * 64 + mt * 16 + g;
#pragma unroll
        for (int nt = 0; nt < 4; nt++) {
            int col = bn + wn * 32 + nt * 8 + t2;
            float4 r = {acc[mt][nt][0], acc[mt][nt][1],
                        acc[mt][nt][2], acc[mt][nt][3]};
            if (EPI >= 1) {
                float b0 = bias[col], b1 = bias[col + 1];
                r.x += b0; r.y += b1; r.z += b0; r.w += b1;
            }
            if (EPI == 2) {
                r.x = fmaxf(r.x, 0.f); r.y = fmaxf(r.y, 0.f);
                r.z = fmaxf(r.z, 0.f); r.w = fmaxf(r.w, 0.f);
            }
            *(float2*)&C[(size_t)row * N + col]       = make_float2(r.x, r.y);
            *(float2*)&C[(size_t)(row + 8) * N + col] = make_float2(r.z, r.w);
        }
    }
}

// ---------------------------------------------------------------------------
// Fused relative attention (fp32)
// ---------------------------------------------------------------------------
#define ATTN_SP   17
#define ATTN_SMEM ((KLEN_*ATTN_SP + 1024 + 1024 + 4096 + 16) * 4)

__global__ __launch_bounds__(256) void attn_kernel(
    const float* __restrict__ q,  const float* __restrict__ kv,
    const float* __restrict__ rk, const float* __restrict__ bw,
    const float* __restrict__ br, float* __restrict__ vec)
{
    extern __shared__ float sm[];
    float* s    = sm;
    float* qw   = sm + KLEN_ * ATTN_SP;
    float* qr   = qw + 1024;
    float* red  = qr + 1024;
    float* sinv = red + 4096;

    const int itile = blockIdx.x, n = blockIdx.y, b = blockIdx.z;
    const int tid = threadIdx.x;
    const int i0 = itile << 4;
    const int cmax = i0 + 528;

    for (int u = tid; u < 1024; u += 256) {
        int i = u >> 6, d = u & 63;
        float qv = q[((size_t)(b * QLEN_ + i0 + i) << 10) + n * 64 + d];
        qw[u] = qv + bw[n * 64 + d];
        qr[u] = qv + br[n * 64 + d];
    }
    __syncthreads();

    for (int j = tid; j < cmax; j += 256) {
        const float4* kp = (const float4*)(kv + ((size_t)(b * KLEN_ + j) << 11) + n * 64);
        float4 kr[16];
#pragma unroll
        for (int u = 0; u < 16; u++) kr[u] = kp[u];
#pragma unroll
        for (int i = 0; i < 16; i++) {
            const float4* qp = (const float4*)(qw + (i << 6));
            float acc = 0.f;
#pragma unroll
            for (int u = 0; u < 16; u++) {
                float4 a = qp[u];
                acc += a.x * kr[u].x + a.y * kr[u].y + a.z * kr[u].z + a.w * kr[u].w;
            }
            s[j * ATTN_SP + i] = acc;
        }
    }
    __syncthreads();

    for (int jr = tid; jr < KLEN_; jr += 256) {
        const float4* rp = (const float4*)(rk + ((size_t)jr << 10) + n * 64);
        float4 rr[16];
#pragma unroll
        for (int u = 0; u < 16; u++) rr[u] = rp[u];
#pragma unroll
        for (int i = 0; i < 16; i++) {
            int j = jr + (i0 + i) - 511;
            if (j >= 0) {
                const float4* qp = (const float4*)(qr + (i << 6));
                float acc = 0.f;
#pragma unroll
                for (int u = 0; u < 16; u++) {
                    float4 a = qp[u];
                    acc += a.x * rr[u].x + a.y * rr[u].y + a.z * rr[u].z + a.w * rr[u].w;
                }
                s[j * ATTN_SP + i] += acc;
            }
        }
    }
    __syncthreads();

    {
        int wid = tid >> 5, lane = tid & 31;
        for (int i = wid; i < 16; i += 8) {
            int count = i0 + i + 513;
            float m = -1e30f;
            for (int j = lane; j < count; j += 32)
                m = fmaxf(m, s[j * ATTN_SP + i]);
#pragma unroll
            for (int o = 16; o; o >>= 1)
                m = fmaxf(m, __shfl_xor_sync(0xffffffffu, m, o));
            float sum = 0.f;
            for (int j = lane; j < count; j += 32) {
                float p = expf((s[j * ATTN_SP + i] - m) * 0.125f);
                s[j * ATTN_SP + i] = p;
                sum += p;
            }
#pragma unroll
            for (int o = 16; o; o >>= 1)
                sum += __shfl_xor_sync(0xffffffffu, sum, o);
            if (lane == 0) sinv[i] = 1.f / sum;
            for (int j = count + lane; j < cmax; j += 32)
                s[j * ATTN_SP + i] = 0.f;
        }
    }
    __syncthreads();

    {
        int d = tid & 63, grp = tid >> 6;
        float acc[16];
#pragma unroll
        for (int i = 0; i < 16; i++) acc[i] = 0.f;
        for (int j = grp; j < cmax; j += 4) {
            float vv = kv[((size_t)(b * KLEN_ + j) << 11) + 1024 + n * 64 + d];
#pragma unroll
            for (int i = 0; i < 16; i++)
                acc[i] += s[j * ATTN_SP + i] * vv;
        }
#pragma unroll
        for (int i = 0; i < 16; i++) red[((grp << 4) + i) * 64 + d] = acc[i];
        __syncthreads();
        if (grp == 0) {
#pragma unroll
            for (int i = 0; i < 16; i++) {
                float r0 = red[i * 64 + d] + red[(16 + i) * 64 + d]
                         + red[(32 + i) * 64 + d] + red[(48 + i) * 64 + d];
                vec[((size_t)(b * QLEN_ + i0 + i) << 10) + n * 64 + d] = r0 * sinv[i];
            }
        }
    }
}

// ---------------------------------------------------------------------------
// x = LayerNorm(x + y) * g + b
// ---------------------------------------------------------------------------
__global__ __launch_bounds__(256) void add_ln_kernel(
    float* __restrict__ x, const float* __restrict__ y,
    const float* __restrict__ g, const float* __restrict__ bb)
{
    int row = blockIdx.x, tid = threadIdx.x;
    float* xr = x + (size_t)row * DMOD;
    const float* yr = y + (size_t)row * DMOD;
    float v[4];
    float s = 0.f, sq = 0.f;
#pragma unroll
    for (int u = 0; u < 4; u++) {
        int idx = tid + (u << 8);
        v[u] = xr[idx] + yr[idx];
        s += v[u]; sq += v[u] * v[u];
    }
#pragma unroll
    for (int o = 16; o; o >>= 1) {
        s  += __shfl_xor_sync(0xffffffffu, s,  o);
        sq += __shfl_xor_sync(0xffffffffu, sq, o);
    }
    __shared__ float ws[8], wq[8];
    if ((tid & 31) == 0) { ws[tid >> 5] = s; wq[tid >> 5] = sq; }
    __syncthreads();
    s = 0.f; sq = 0.f;
#pragma unroll
    for (int u = 0; u < 8; u++) { s += ws[u]; sq += wq[u]; }
    float mu   = s * (1.f / DMOD);
    float var  = sq * (1.f / DMOD) - mu * mu;
    float rstd = rsqrtf(var + 1e-5f);
#pragma unroll
    for (int u = 0; u < 4; u++) {
        int idx = tid + (u << 8);
        xr[idx] = (v[u] - mu) * rstd * g[idx] + bb[idx];
    }
}

// ---------------------------------------------------------------------------
// NLL
// ---------------------------------------------------------------------------
__global__ __launch_bounds__(256) void nll_kernel(
    const float* __restrict__ logits, const int* __restrict__ target,
    float* __restrict__ out)
{
    int row = blockIdx.x, tid = threadIdx.x;
    const float* lr = logits + (size_t)row * VOCAB;

    float m = -1e30f;
    for (int j = tid; j < VOCAB; j += 256) m = fmaxf(m, lr[j]);
#pragma unroll
    for (int o = 16; o; o >>= 1) m = fmaxf(m, __shfl_xor_sync(0xffffffffu, m, o));
    __shared__ float wm[8];
    if ((tid & 31) == 0) wm[tid >> 5] = m;
    __syncthreads();
#pragma unroll
    for (int u = 0; u < 8; u++) m = fmaxf(m, wm[u]);

    float s = 0.f;
    for (int j = tid; j < VOCAB; j += 256) s += expf(lr[j] - m);
#pragma unroll
    for (int o = 16; o; o >>= 1) s += __shfl_xor_sync(0xffffffffu, s, o);
    __shared__ float wsum[8];
    if ((tid & 31) == 0) wsum[tid >> 5] = s;
    __syncthreads();

    if (tid == 0) {
        float tot = 0.f;
#pragma unroll
        for (int u = 0; u < 8; u++) tot += wsum[u];
        out[row] = -(lr[target[row]] - m - logf(tot));
    }
}

// ---------------------------------------------------------------------------
// Orchestration
// ---------------------------------------------------------------------------
extern "C" void kernel_launch(void* const* d_in, const int* in_sizes, int n_in,
                              void* d_out, int out_size)
{
    const int*   data   = (const int*)  d_in[0];
    const int*   target = (const int*)  d_in[1];
    const float* memory = (const float*)d_in[2];
    const float* emb    = (const float*)d_in[3];
    const float* Wq     = (const float*)d_in[4];
    const float* Wkv    = (const float*)d_in[5];
    const float* Wr     = (const float*)d_in[6];
    const float* Wo     = (const float*)d_in[7];
    const float* W1     = (const float*)d_in[8];
    const float* b1     = (const float*)d_in[9];
    const float* W2     = (const float*)d_in[10];
    const float* b2     = (const float*)d_in[11];
    const float* g1     = (const float*)d_in[12];
    const float* be1    = (const float*)d_in[13];
    const float* g2     = (const float*)d_in[14];
    const float* be2    = (const float*)d_in[15];
    const float* bw     = (const float*)d_in[16];
    const float* brr    = (const float*)d_in[17];
    float* out = (float*)d_out;

    float *x, *xc, *qb, *kvb, *rkb, *pos, *vecb, *tmp, *ffh, *lg;
    cudaGetSymbolAddress((void**)&x,    g_x);
    cudaGetSymbolAddress((void**)&xc,   g_xcat);
    cudaGetSymbolAddress((void**)&qb,   g_q);
    cudaGetSymbolAddress((void**)&kvb,  g_kv);
    cudaGetSymbolAddress((void**)&rkb,  g_rk);
    cudaGetSymbolAddress((void**)&pos,  g_pos);
    cudaGetSymbolAddress((void**)&vecb, g_vec);
    cudaGetSymbolAddress((void**)&tmp,  g_tmp);
    cudaGetSymbolAddress((void**)&ffh,  g_ffh);
    cudaGetSymbolAddress((void**)&lg,   g_lgt);

    cudaFuncSetAttribute(attn_kernel,
                         cudaFuncAttributeMaxDynamicSharedMemorySize, ATTN_SMEM);

    embed_kernel <<<NROWS, 256>>>(data, emb, x);
    posemb_kernel<<<KLEN_, 512>>>(pos);

    for (int l = 0; l < NLYR; l++) {
        const float* memL = memory + (size_t)l * BSZ_ * QLEN_ * DMOD;

        concat_kernel<<<NCROWS, 256>>>(memL, x, xc);

        // q = x @ Wq[l]                          [2048,1024] x [1024,1024]
        gemm_bf16<0, false><<<dim3(8, 16), 256>>>(
            x, Wq + (size_t)l * DMOD * DMOD, nullptr, qb, NROWS, DMOD, DMOD);
        // kv = xcat @ Wkv[l]                     [4096,1024] x [1024,2048]
        gemm_bf16<0, false><<<dim3(16, 32), 256>>>(
            xc, Wkv + (size_t)l * DMOD * 2 * DMOD, nullptr, kvb, NCROWS, 2 * DMOD, DMOD);
        // rk = pos @ Wr[l]                       [1024,1024] x [1024,1024]
        gemm_bf16<0, false><<<dim3(8, 8), 256>>>(
            pos, Wr + (size_t)l * DMOD * DMOD, nullptr, rkb, KLEN_, DMOD, DMOD);

        attn_kernel<<<dim3(32, 16, 4), 256, ATTN_SMEM>>>(qb, kvb, rkb, bw, brr, vecb);

        // attn_out = vec @ Wo[l]
        gemm_bf16<0, false><<<dim3(8, 16), 256>>>(
            vecb, Wo + (size_t)l * DMOD * DMOD, nullptr, tmp, NROWS, DMOD, DMOD);
        add_ln_kernel<<<NROWS, 256>>>(x, tmp, g1 + l * DMOD, be1 + l * DMOD);

        // ff = relu(x @ W1 + b1) @ W2 + b2
        gemm_bf16<2, false><<<dim3(32, 16), 256>>>(
            x, W1 + (size_t)l * DMOD * DINNER, b1 + (size_t)l * DINNER,
            ffh, NROWS, DINNER, DMOD);
        gemm_bf16<1, false><<<dim3(8, 16), 256>>>(
            ffh, W2 + (size_t)l * DINNER * DMOD, b2 + (size_t)l * DMOD,
            tmp, NROWS, DMOD, DINNER);
        add_ln_kernel<<<NROWS, 256>>>(x, tmp, g2 + l * DMOD, be2 + l * DMOD);
    }

    // logits = x @ emb^T   [2048,1024] x [32000,1024]^T
    gemm_bf16<0, true><<<dim3(VOCAB / 128, 16), 256>>>(
        x, emb, nullptr, lg, NROWS, VOCAB, DMOD);

    nll_kernel<<<NROWS, 256>>>(lg, target, out);
}

// round 16
// speedup vs baseline: 1.0191x; 1.0191x over previous
#include <cuda_runtime.h>
#include <math.h>
#include <stdint.h>

// ---------------------------------------------------------------------------
// Problem constants
// ---------------------------------------------------------------------------
#define NLYR   6
#define BSZ_   4
#define QLEN_  512
#define KLEN_  1024
#define DMOD   1024
#define NHEAD  16
#define DHEAD  64
#define DINNER 4096
#define VOCAB  32000
#define NROWS  (BSZ_ * QLEN_)      /* 2048 */
#define NCROWS (BSZ_ * KLEN_)      /* 4096 */

// ---------------------------------------------------------------------------
// Scratch (static device globals — allocation-free)
// ---------------------------------------------------------------------------
__device__ float g_x    [NROWS  * DMOD];
__device__ float g_xcat [NCROWS * DMOD];
__device__ float g_q    [NROWS  * DMOD];
__device__ float g_kv   [NCROWS * 2 * DMOD];
__device__ float g_rk   [KLEN_  * DMOD];
__device__ float g_pos  [KLEN_  * DMOD];
__device__ float g_vec  [NROWS  * DMOD];
__device__ float g_tmp  [NROWS  * DMOD];
__device__ float g_ffh  [NROWS  * DINNER];
__device__ float g_lgt  [(size_t)NROWS * VOCAB];

// ---------------------------------------------------------------------------
// Small helpers
// ---------------------------------------------------------------------------
__device__ __forceinline__ uint32_t pack_bf2(float lo, float hi) {
    uint32_t u;
    asm("cvt.rn.bf16x2.f32 %0, %1, %2;" : "=r"(u) : "f"(hi), "f"(lo));
    return u;
}

__device__ __forceinline__ void mma16(float* d, const uint32_t* a, const uint32_t* b) {
    asm volatile(
        "mma.sync.aligned.m16n8k16.row.col.f32.bf16.bf16.f32 "
        "{%0,%1,%2,%3}, {%4,%5,%6,%7}, {%8,%9}, {%0,%1,%2,%3};\n"
        : "+f"(d[0]), "+f"(d[1]), "+f"(d[2]), "+f"(d[3])
        : "r"(a[0]), "r"(a[1]), "r"(a[2]), "r"(a[3]), "r"(b[0]), "r"(b[1]));
}

// ---------------------------------------------------------------------------
// Embedding gather
// ---------------------------------------------------------------------------
__global__ __launch_bounds__(256) void embed_kernel(
    const int* __restrict__ data, const float* __restrict__ emb,
    float* __restrict__ x)
{
    int row = blockIdx.x;
    int tok = data[row];
    const float4* src = (const float4*)(emb + (size_t)tok * DMOD);
    float4*       dst = (float4*)(x + (size_t)row * DMOD);
    dst[threadIdx.x] = src[threadIdx.x];
}

// ---------------------------------------------------------------------------
// Positional embedding
// ---------------------------------------------------------------------------
__global__ __launch_bounds__(512) void posemb_kernel(float* __restrict__ pos)
{
    int p = blockIdx.x;
    int f = threadIdx.x;
    double invf = exp(-((double)(2 * f) / 1024.0) * log(10000.0));
    float ang = (float)((double)(KLEN_ - 1 - p) * invf);
    pos[(size_t)p * DMOD + f]       = sinf(ang);
    pos[(size_t)p * DMOD + 512 + f] = cosf(ang);
}

// ---------------------------------------------------------------------------
// Concat [mem ; x]
// ---------------------------------------------------------------------------
__global__ __launch_bounds__(256) void concat_kernel(
    const float* __restrict__ mem, const float* __restrict__ x,
    float* __restrict__ xc)
{
    int row = blockIdx.x;
    int b = row >> 10, j = row & 1023;
    const float4* src = (j < QLEN_)
        ? (const float4*)(mem + ((size_t)b * QLEN_ + j) * DMOD)
        : (const float4*)(x   + ((size_t)b * QLEN_ + (j - QLEN_)) * DMOD);
    float4* dst = (float4*)(xc + (size_t)row * DMOD);
    dst[threadIdx.x] = src[threadIdx.x];
}

// ---------------------------------------------------------------------------
// BF16 tensor-core GEMM (fp32 in/out, bf16 compute, fp32 accumulate).
//   C[M,N] = A[M,K] @ B     (BT=false: B is [K,N];  BT=true: B is [N,K], C=A@B^T)
// Block tile 64x128x32, 256 threads = 8 warps (2m x 4n), warp tile 32x32,
// mma.m16n8k16, register gmem prefetch (R13 pipeline), 2 CTAs/SM
// (acc 2x4x4 = 32 regs -> fits <=128 regs; smem 12 KB/CTA).
// Fragment smem layouts (validated in R13):
//   A: per (16-row tile mtg, k16-step ks) segment seg=mtg*2+ks; lane^(seg&7)
//      holds uint4 {a0,a1,a2,a3}. 8 segs x 32 lanes x uint4 = 4 KB.
//   B: per (8-col tile ntg, k16-step ks) segment; lane^(ntg&15) holds uint2.
// Requires M%64==0, N%128==0, K%32==0. EPI: 0=none, 1=+bias, 2=relu(+bias)
// ---------------------------------------------------------------------------
template<int EPI, bool BT>
__global__ __launch_bounds__(256, 2) void gemm_bf16(
    const float* __restrict__ A, const float* __restrict__ Bm,
    const float* __restrict__ bias, float* __restrict__ C,
    int M, int N, int K)
{
    __shared__ __align__(16) uint32_t As[1024];   // 4 KB
    __shared__ __align__(16) uint32_t Bs[2048];   // 8 KB

    const int tid  = threadIdx.x;
    const int lane = tid & 31;
    const int wid  = tid >> 5;
    const int wm   = wid >> 2;          // 0..1 (32 rows each)
    const int wn   = wid & 3;           // 0..3 (32 cols each)
    const int bm   = blockIdx.y << 6;
    const int bn   = blockIdx.x << 7;

    // ---- A loader: row = tid>>2 (64 rows), 8 k at (tid&3)*8 ---------------
    const int arow = tid >> 2;
    const float* Ap = A + (size_t)(bm + arow) * K + ((tid & 3) << 3);

    // ---- B loader (identical to R13) ---------------------------------------
    const float* Bp;
    if (BT) {
        Bp = Bm + (size_t)(bn + (tid >> 1)) * K + ((tid & 1) << 4);
    } else {
        Bp = Bm + (size_t)((tid >> 4) << 1) * N + bn + ((tid & 15) << 3);
    }

    float4 ra[2], rb[4];
    ra[0] = ((const float4*)Ap)[0];
    ra[1] = ((const float4*)Ap)[1];
    if (BT) {
#pragma unroll
        for (int u = 0; u < 4; u++) rb[u] = ((const float4*)Bp)[u];
    } else {
        rb[0] = ((const float4*)Bp)[0];
        rb[1] = ((const float4*)Bp)[1];
        rb[2] = ((const float4*)(Bp + N))[0];
        rb[3] = ((const float4*)(Bp + N))[1];
    }

    float acc[2][4][4];
#pragma unroll
    for (int mt = 0; mt < 2; mt++)
#pragma unroll
        for (int nt = 0; nt < 4; nt++)
#pragma unroll
            for (int r = 0; r < 4; r++) acc[mt][nt][r] = 0.f;

    const int nk = K >> 5;

    for (int kt = 0; kt < nk; kt++) {
        // ---- scatter A (this thread owns one k8 half of one k16) ----------
        {
            const int mtg = arow >> 4, r16 = arow & 15;
            const int g = r16 & 7, hb = r16 >> 3;
            const int ks = (tid & 3) >> 1;          // which k16
            const int kh = tid & 1;                 // which k8 half
            const int seg = (mtg << 1) + ks;
            const int v = seg & 7;
            float vv[8] = {ra[0].x, ra[0].y, ra[0].z, ra[0].w,
                           ra[1].x, ra[1].y, ra[1].z, ra[1].w};
#pragma unroll
            for (int t = 0; t < 4; t++) {
                int ls = ((g << 2) + t) ^ v;
                As[(((seg << 5) + ls) << 2) + hb + (kh << 1)] =
                    pack_bf2(vv[2 * t], vv[2 * t + 1]);
            }
        }
        // ---- scatter B (identical to R13) -----------------------------------
        if (BT) {
            const int n = tid >> 1;
            const int g = n & 7, ntg = n >> 3;
            const int ks = tid & 1;
            const int segB = (ntg << 1) + ks;
            const int v = ntg & 15;
            float vv[16] = {rb[0].x, rb[0].y, rb[0].z, rb[0].w,
                            rb[1].x, rb[1].y, rb[1].z, rb[1].w,
                            rb[2].x, rb[2].y, rb[2].z, rb[2].w,
                            rb[3].x, rb[3].y, rb[3].z, rb[3].w};
#pragma unroll
            for (int p = 0; p < 8; p++) {
                int t = p & 3, breg = p >> 2;
                int ls = ((g << 2) + t) ^ v;
                Bs[(((segB << 5) + ls) << 1) + breg] =
                    pack_bf2(vv[2 * p], vv[2 * p + 1]);
            }
        } else {
            const int kp = tid >> 4;
            const int cg = tid & 15;
            const int ks = kp >> 3, t = kp & 3, breg = (kp >> 2) & 1;
            const int segB = (cg << 1) + ks;
            const int v = cg & 15;
            float r0[8] = {rb[0].x, rb[0].y, rb[0].z, rb[0].w,
                           rb[1].x, rb[1].y, rb[1].z, rb[1].w};
            float r1[8] = {rb[2].x, rb[2].y, rb[2].z, rb[2].w,
                           rb[3].x, rb[3].y, rb[3].z, rb[3].w};
#pragma unroll
            for (int j = 0; j < 8; j++) {
                int ls = ((j << 2) + t) ^ v;
                Bs[(((segB << 5) + ls) << 1) + breg] = pack_bf2(r0[j], r1[j]);
            }
        }
        __syncthreads();

        // ---- prefetch next ktile into registers -----------------------------
        if (kt + 1 < nk) {
            const float* Ap2 = Ap + (size_t)(kt + 1) * 32;
            ra[0] = ((const float4*)Ap2)[0];
            ra[1] = ((const float4*)Ap2)[1];
            if (BT) {
                const float* Bp2 = Bp + (size_t)(kt + 1) * 32;
#pragma unroll
                for (int u = 0; u < 4; u++) rb[u] = ((const float4*)Bp2)[u];
            } else {
                const float* Bp2 = Bp + (size_t)(kt + 1) * 32 * N;
                rb[0] = ((const float4*)Bp2)[0];
                rb[1] = ((const float4*)Bp2)[1];
                rb[2] = ((const float4*)(Bp2 + N))[0];
                rb[3] = ((const float4*)(Bp2 + N))[1];
            }
        }

        // ---- compute ----------------------------------------------------------
#pragma unroll
        for (int ks = 0; ks < 2; ks++) {
            uint4 af[2];
            uint2 bf[4];
#pragma unroll
            for (int mt = 0; mt < 2; mt++) {
                int seg = (((wm << 1) + mt) << 1) + ks;
                af[mt] = ((const uint4*)As)[(seg << 5) + (lane ^ (seg & 7))];
            }
#pragma unroll
            for (int nt = 0; nt < 4; nt++) {
                int ntg = (wn << 2) + nt;
                int segB = (ntg << 1) + ks;
                bf[nt] = ((const uint2*)Bs)[(segB << 5) + (lane ^ (ntg & 15))];
            }
#pragma unroll
            for (int mt = 0; mt < 2; mt++)
#pragma unroll
                for (int nt = 0; nt < 4; nt++)
                    mma16(acc[mt][nt], (const uint32_t*)&af[mt],
                          (const uint32_t*)&bf[nt]);
        }
        __syncthreads();
    }

    // ---- epilogue -------------------------------------------------------------
    const int g  = lane >> 2;
    const int t2 = (lane & 3) << 1;
#pragma unroll
    for (int mt = 0; mt < 2; mt++) {
        int row = bm + wm * 32 + mt * 16 + g;
#pragma unroll
        for (int nt = 0; nt < 4; nt++) {
            int col = bn + wn * 32 + nt * 8 + t2;
            float4 r = {acc[mt][nt][0], acc[mt][nt][1],
                        acc[mt][nt][2], acc[mt][nt][3]};
            if (EPI >= 1) {
                float b0 = bias[col], b1 = bias[col + 1];
                r.x += b0; r.y += b1; r.z += b0; r.w += b1;
            }
            if (EPI == 2) {
                r.x = fmaxf(r.x, 0.f); r.y = fmaxf(r.y, 0.f);
                r.z = fmaxf(r.z, 0.f); r.w = fmaxf(r.w, 0.f);
            }
            *(float2*)&C[(size_t)row * N + col]       = make_float2(r.x, r.y);
            *(float2*)&C[(size_t)(row + 8) * N + col] = make_float2(r.z, r.w);
        }
    }
}

// ---------------------------------------------------------------------------
// Fused relative attention (fp32)
// ---------------------------------------------------------------------------
#define ATTN_SP   17
#define ATTN_SMEM ((KLEN_*ATTN_SP + 1024 + 1024 + 4096 + 16) * 4)

__global__ __launch_bounds__(256) void attn_kernel(
    const float* __restrict__ q,  const float* __restrict__ kv,
    const float* __restrict__ rk, const float* __restrict__ bw,
    const float* __restrict__ br, float* __restrict__ vec)
{
    extern __shared__ float sm[];
    float* s    = sm;
    float* qw   = sm + KLEN_ * ATTN_SP;
    float* qr   = qw + 1024;
    float* red  = qr + 1024;
    float* sinv = red + 4096;

    const int itile = blockIdx.x, n = blockIdx.y, b = blockIdx.z;
    const int tid = threadIdx.x;
    const int i0 = itile << 4;
    const int cmax = i0 + 528;

    for (int u = tid; u < 1024; u += 256) {
        int i = u >> 6, d = u & 63;
        float qv = q[((size_t)(b * QLEN_ + i0 + i) << 10) + n * 64 + d];
        qw[u] = qv + bw[n * 64 + d];
        qr[u] = qv + br[n * 64 + d];
    }
    __syncthreads();

    for (int j = tid; j < cmax; j += 256) {
        const float4* kp = (const float4*)(kv + ((size_t)(b * KLEN_ + j) << 11) + n * 64);
        float4 kr[16];
#pragma unroll
        for (int u = 0; u < 16; u++) kr[u] = kp[u];
#pragma unroll
        for (int i = 0; i < 16; i++) {
            const float4* qp = (const float4*)(qw + (i << 6));
            float acc = 0.f;
#pragma unroll
            for (int u = 0; u < 16; u++) {
                float4 a = qp[u];
                acc += a.x * kr[u].x + a.y * kr[u].y + a.z * kr[u].z + a.w * kr[u].w;
            }
            s[j * ATTN_SP + i] = acc;
        }
    }
    __syncthreads();

    for (int jr = tid; jr < KLEN_; jr += 256) {
        const float4* rp = (const float4*)(rk + ((size_t)jr << 10) + n * 64);
        float4 rr[16];
#pragma unroll
        for (int u = 0; u < 16; u++) rr[u] = rp[u];
#pragma unroll
        for (int i = 0; i < 16; i++) {
            int j = jr + (i0 + i) - 511;
            if (j >= 0) {
                const float4* qp = (const float4*)(qr + (i << 6));
                float acc = 0.f;
#pragma unroll
                for (int u = 0; u < 16; u++) {
                    float4 a = qp[u];
                    acc += a.x * rr[u].x + a.y * rr[u].y + a.z * rr[u].z + a.w * rr[u].w;
                }
                s[j * ATTN_SP + i] += acc;
            }
        }
    }
    __syncthreads();

    {
        int wid = tid >> 5, lane = tid & 31;
        for (int i = wid; i < 16; i += 8) {
            int count = i0 + i + 513;
            float m = -1e30f;
            for (int j = lane; j < count; j += 32)
                m = fmaxf(m, s[j * ATTN_SP + i]);
#pragma unroll
            for (int o = 16; o; o >>= 1)
                m = fmaxf(m, __shfl_xor_sync(0xffffffffu, m, o));
            float sum = 0.f;
            for (int j = lane; j < count; j += 32) {
                float p = expf((s[j * ATTN_SP + i] - m) * 0.125f);
                s[j * ATTN_SP + i] = p;
                sum += p;
            }
#pragma unroll
            for (int o = 16; o; o >>= 1)
                sum += __shfl_xor_sync(0xffffffffu, sum, o);
            if (lane == 0) sinv[i] = 1.f / sum;
            for (int j = count + lane; j < cmax; j += 32)
                s[j * ATTN_SP + i] = 0.f;
        }
    }
    __syncthreads();

    {
        int d = tid & 63, grp = tid >> 6;
        float acc[16];
#pragma unroll
        for (int i = 0; i < 16; i++) acc[i] = 0.f;
        for (int j = grp; j < cmax; j += 4) {
            float vv = kv[((size_t)(b * KLEN_ + j) << 11) + 1024 + n * 64 + d];
#pragma unroll
            for (int i = 0; i < 16; i++)
                acc[i] += s[j * ATTN_SP + i] * vv;
        }
#pragma unroll
        for (int i = 0; i < 16; i++) red[((grp << 4) + i) * 64 + d] = acc[i];
        __syncthreads();
        if (grp == 0) {
#pragma unroll
            for (int i = 0; i < 16; i++) {
                float r0 = red[i * 64 + d] + red[(16 + i) * 64 + d]
                         + red[(32 + i) * 64 + d] + red[(48 + i) * 64 + d];
                vec[((size_t)(b * QLEN_ + i0 + i) << 10) + n * 64 + d] = r0 * sinv[i];
            }
        }
    }
}

// ---------------------------------------------------------------------------
// x = LayerNorm(x + y) * g + b
// ---------------------------------------------------------------------------
__global__ __launch_bounds__(256) void add_ln_kernel(
    float* __restrict__ x, const float* __restrict__ y,
    const float* __restrict__ g, const float* __restrict__ bb)
{
    int row = blockIdx.x, tid = threadIdx.x;
    float* xr = x + (size_t)row * DMOD;
    const float* yr = y + (size_t)row * DMOD;
    float v[4];
    float s = 0.f, sq = 0.f;
#pragma unroll
    for (int u = 0; u < 4; u++) {
        int idx = tid + (u << 8);
        v[u] = xr[idx] + yr[idx];
        s += v[u]; sq += v[u] * v[u];
    }
#pragma unroll
    for (int o = 16; o; o >>= 1) {
        s  += __shfl_xor_sync(0xffffffffu, s,  o);
        sq += __shfl_xor_sync(0xffffffffu, sq, o);
    }
    __shared__ float ws[8], wq[8];
    if ((tid & 31) == 0) { ws[tid >> 5] = s; wq[tid >> 5] = sq; }
    __syncthreads();
    s = 0.f; sq = 0.f;
#pragma unroll
    for (int u = 0; u < 8; u++) { s += ws[u]; sq += wq[u]; }
    float mu   = s * (1.f / DMOD);
    float var  = sq * (1.f / DMOD) - mu * mu;
    float rstd = rsqrtf(var + 1e-5f);
#pragma unroll
    for (int u = 0; u < 4; u++) {
        int idx = tid + (u << 8);
        xr[idx] = (v[u] - mu) * rstd * g[idx] + bb[idx];
    }
}

// ---------------------------------------------------------------------------
// NLL
// ---------------------------------------------------------------------------
__global__ __launch_bounds__(256) void nll_kernel(
    const float* __restrict__ logits, const int* __restrict__ target,
    float* __restrict__ out)
{
    int row = blockIdx.x, tid = threadIdx.x;
    const float* lr = logits + (size_t)row * VOCAB;

    float m = -1e30f;
    for (int j = tid; j < VOCAB; j += 256) m = fmaxf(m, lr[j]);
#pragma unroll
    for (int o = 16; o; o >>= 1) m = fmaxf(m, __shfl_xor_sync(0xffffffffu, m, o));
    __shared__ float wm[8];
    if ((tid & 31) == 0) wm[tid >> 5] = m;
    __syncthreads();
#pragma unroll
    for (int u = 0; u < 8; u++) m = fmaxf(m, wm[u]);

    float s = 0.f;
    for (int j = tid; j < VOCAB; j += 256) s += expf(lr[j] - m);
#pragma unroll
    for (int o = 16; o; o >>= 1) s += __shfl_xor_sync(0xffffffffu, s, o);
    __shared__ float wsum[8];
    if ((tid & 31) == 0) wsum[tid >> 5] = s;
    __syncthreads();

    if (tid == 0) {
        float tot = 0.f;
#pragma unroll
        for (int u = 0; u < 8; u++) tot += wsum[u];
        out[row] = -(lr[target[row]] - m - logf(tot));
    }
}

// ---------------------------------------------------------------------------
// Orchestration
// ---------------------------------------------------------------------------
extern "C" void kernel_launch(void* const* d_in, const int* in_sizes, int n_in,
                              void* d_out, int out_size)
{
    const int*   data   = (const int*)  d_in[0];
    const int*   target = (const int*)  d_in[1];
    const float* memory = (const float*)d_in[2];
    const float* emb    = (const float*)d_in[3];
    const float* Wq     = (const float*)d_in[4];
    const float* Wkv    = (const float*)d_in[5];
    const float* Wr     = (const float*)d_in[6];
    const float* Wo     = (const float*)d_in[7];
    const float* W1     = (const float*)d_in[8];
    const float* b1     = (const float*)d_in[9];
    const float* W2     = (const float*)d_in[10];
    const float* b2     = (const float*)d_in[11];
    const float* g1     = (const float*)d_in[12];
    const float* be1    = (const float*)d_in[13];
    const float* g2     = (const float*)d_in[14];
    const float* be2    = (const float*)d_in[15];
    const float* bw     = (const float*)d_in[16];
    const float* brr    = (const float*)d_in[17];
    float* out = (float*)d_out;

    float *x, *xc, *qb, *kvb, *rkb, *pos, *vecb, *tmp, *ffh, *lg;
    cudaGetSymbolAddress((void**)&x,    g_x);
    cudaGetSymbolAddress((void**)&xc,   g_xcat);
    cudaGetSymbolAddress((void**)&qb,   g_q);
    cudaGetSymbolAddress((void**)&kvb,  g_kv);
    cudaGetSymbolAddress((void**)&rkb,  g_rk);
    cudaGetSymbolAddress((void**)&pos,  g_pos);
    cudaGetSymbolAddress((void**)&vecb, g_vec);
    cudaGetSymbolAddress((void**)&tmp,  g_tmp);
    cudaGetSymbolAddress((void**)&ffh,  g_ffh);
    cudaGetSymbolAddress((void**)&lg,   g_lgt);

    cudaFuncSetAttribute(attn_kernel,
                         cudaFuncAttributeMaxDynamicSharedMemorySize, ATTN_SMEM);

    embed_kernel <<<NROWS, 256>>>(data, emb, x);
    posemb_kernel<<<KLEN_, 512>>>(pos);

    for (int l = 0; l < NLYR; l++) {
        const float* memL = memory + (size_t)l * BSZ_ * QLEN_ * DMOD;

        concat_kernel<<<NCROWS, 256>>>(memL, x, xc);

        // q = x @ Wq[l]                          [2048,1024] x [1024,1024]
        gemm_bf16<0, false><<<dim3(8, 32), 256>>>(
            x, Wq + (size_t)l * DMOD * DMOD, nullptr, qb, NROWS, DMOD, DMOD);
        // kv = xcat @ Wkv[l]                     [4096,1024] x [1024,2048]
        gemm_bf16<0, false><<<dim3(16, 64), 256>>>(
            xc, Wkv + (size_t)l * DMOD * 2 * DMOD, nullptr, kvb, NCROWS, 2 * DMOD, DMOD);
        // rk = pos @ Wr[l]                       [1024,1024] x [1024,1024]
        gemm_bf16<0, false><<<dim3(8, 16), 256>>>(
            pos, Wr + (size_t)l * DMOD * DMOD, nullptr, rkb, KLEN_, DMOD, DMOD);

        attn_kernel<<<dim3(32, 16, 4), 256, ATTN_SMEM>>>(qb, kvb, rkb, bw, brr, vecb);

        // attn_out = vec @ Wo[l]
        gemm_bf16<0, false><<<dim3(8, 32), 256>>>(
            vecb, Wo + (size_t)l * DMOD * DMOD, nullptr, tmp, NROWS, DMOD, DMOD);
        add_ln_kernel<<<NROWS, 256>>>(x, tmp, g1 + l * DMOD, be1 + l * DMOD);

        // ff = relu(x @ W1 + b1) @ W2 + b2
        gemm_bf16<2, false><<<dim3(32, 32), 256>>>(
            x, W1 + (size_t)l * DMOD * DINNER, b1 + (size_t)l * DINNER,
            ffh, NROWS, DINNER, DMOD);
        gemm_bf16<1, false><<<dim3(8, 32), 256>>>(
            ffh, W2 + (size_t)l * DINNER * DMOD, b2 + (size_t)l * DMOD,
            tmp, NROWS, DMOD, DINNER);
        add_ln_kernel<<<NROWS, 256>>>(x, tmp, g2 + l * DMOD, be2 + l * DMOD);
    }

    // logits = x @ emb^T   [2048,1024] x [32000,1024]^T
    gemm_bf16<0, true><<<dim3(VOCAB / 128, 32), 256>>>(
        x, emb, nullptr, lg, NROWS, VOCAB, DMOD);

    nll_kernel<<<NROWS, 256>>>(lg, target, out);
}

// round 17
// speedup vs baseline: 1.2505x; 1.2270x over previous
#include <cuda_runtime.h>
#include <math.h>
#include <stdint.h>

// ---------------------------------------------------------------------------
// Problem constants
// ---------------------------------------------------------------------------
#define NLYR   6
#define BSZ_   4
#define QLEN_  512
#define KLEN_  1024
#define DMOD   1024
#define NHEAD  16
#define DHEAD  64
#define DINNER 4096
#define VOCAB  32000
#define NROWS  (BSZ_ * QLEN_)      /* 2048 */
#define NCROWS (BSZ_ * KLEN_)      /* 4096 */

// ---------------------------------------------------------------------------
// Scratch (static device globals — allocation-free)
// ---------------------------------------------------------------------------
__device__ float g_x    [NROWS  * DMOD];
__device__ float g_xcat [NCROWS * DMOD];
__device__ float g_q    [NROWS  * DMOD];
__device__ float g_kv   [NCROWS * 2 * DMOD];
__device__ float g_rk   [KLEN_  * DMOD];
__device__ float g_pos  [KLEN_  * DMOD];
__device__ float g_vec  [NROWS  * DMOD];
__device__ float g_tmp  [NROWS  * DMOD];
__device__ float g_ffh  [NROWS  * DINNER];
__device__ float g_lgt  [(size_t)NROWS * VOCAB];

// ---------------------------------------------------------------------------
// Small helpers
// ---------------------------------------------------------------------------
__device__ __forceinline__ uint32_t pack_bf2(float lo, float hi) {
    uint32_t u;
    asm("cvt.rn.bf16x2.f32 %0, %1, %2;" : "=r"(u) : "f"(hi), "f"(lo));
    return u;
}

__device__ __forceinline__ void mma16(float* d, const uint32_t* a, const uint32_t* b) {
    asm volatile(
        "mma.sync.aligned.m16n8k16.row.col.f32.bf16.bf16.f32 "
        "{%0,%1,%2,%3}, {%4,%5,%6,%7}, {%8,%9}, {%0,%1,%2,%3};\n"
        : "+f"(d[0]), "+f"(d[1]), "+f"(d[2]), "+f"(d[3])
        : "r"(a[0]), "r"(a[1]), "r"(a[2]), "r"(a[3]), "r"(b[0]), "r"(b[1]));
}

// ---------------------------------------------------------------------------
// Embedding gather
// ---------------------------------------------------------------------------
__global__ __launch_bounds__(256) void embed_kernel(
    const int* __restrict__ data, const float* __restrict__ emb,
    float* __restrict__ x)
{
    int row = blockIdx.x;
    int tok = data[row];
    const float4* src = (const float4*)(emb + (size_t)tok * DMOD);
    float4*       dst = (float4*)(x + (size_t)row * DMOD);
    dst[threadIdx.x] = src[threadIdx.x];
}

// ---------------------------------------------------------------------------
// Positional embedding
// ---------------------------------------------------------------------------
__global__ __launch_bounds__(512) void posemb_kernel(float* __restrict__ pos)
{
    int p = blockIdx.x;
    int f = threadIdx.x;
    double invf = exp(-((double)(2 * f) / 1024.0) * log(10000.0));
    float ang = (float)((double)(KLEN_ - 1 - p) * invf);
    pos[(size_t)p * DMOD + f]       = sinf(ang);
    pos[(size_t)p * DMOD + 512 + f] = cosf(ang);
}

// ---------------------------------------------------------------------------
// Concat [mem ; x]
// ---------------------------------------------------------------------------
__global__ __launch_bounds__(256) void concat_kernel(
    const float* __restrict__ mem, const float* __restrict__ x,
    float* __restrict__ xc)
{
    int row = blockIdx.x;
    int b = row >> 10, j = row & 1023;
    const float4* src = (j < QLEN_)
        ? (const float4*)(mem + ((size_t)b * QLEN_ + j) * DMOD)
        : (const float4*)(x   + ((size_t)b * QLEN_ + (j - QLEN_)) * DMOD);
    float4* dst = (float4*)(xc + (size_t)row * DMOD);
    dst[threadIdx.x] = src[threadIdx.x];
}

// ---------------------------------------------------------------------------
// BF16 tensor-core GEMM — exact R13 winner (measured 39.7us on q-GEMM).
//   C[M,N] = A[M,K] @ B     (BT=false: B is [K,N];  BT=true: B is [N,K], C=A@B^T)
// Block tile 128x128x32, 256 threads = 8 warps (2m x 4n), warp tile 64x32,
// mma.m16n8k16, single-buffer with register gmem prefetch.
// Requires M%128==0, N%128==0, K%32==0. EPI: 0=none, 1=+bias, 2=relu(+bias)
// ---------------------------------------------------------------------------
template<int EPI, bool BT>
__global__ __launch_bounds__(256, 1) void gemm_bf16(
    const float* __restrict__ A, const float* __restrict__ Bm,
    const float* __restrict__ bias, float* __restrict__ C,
    int M, int N, int K)
{
    __shared__ __align__(16) uint32_t As[2048];   // 8 KB
    __shared__ __align__(16) uint32_t Bs[2048];   // 8 KB

    const int tid  = threadIdx.x;
    const int lane = tid & 31;
    const int wid  = tid >> 5;
    const int wm   = wid >> 2;
    const int wn   = wid & 3;
    const int bm   = blockIdx.y << 7;
    const int bn   = blockIdx.x << 7;

    const int arow = tid >> 1;
    const int acb  = (tid & 1) << 4;
    const float* Ap = A + (size_t)(bm + arow) * K + acb;

    const float* Bp;
    if (BT) {
        Bp = Bm + (size_t)(bn + (tid >> 1)) * K + ((tid & 1) << 4);
    } else {
        Bp = Bm + (size_t)((tid >> 4) << 1) * N + bn + ((tid & 15) << 3);
    }

    float4 ra[4], rb[4];
#pragma unroll
    for (int u = 0; u < 4; u++) ra[u] = ((const float4*)Ap)[u];
    if (BT) {
#pragma unroll
        for (int u = 0; u < 4; u++) rb[u] = ((const float4*)Bp)[u];
    } else {
        rb[0] = ((const float4*)Bp)[0];
        rb[1] = ((const float4*)Bp)[1];
        rb[2] = ((const float4*)(Bp + N))[0];
        rb[3] = ((const float4*)(Bp + N))[1];
    }

    float acc[4][4][4];
#pragma unroll
    for (int mt = 0; mt < 4; mt++)
#pragma unroll
        for (int nt = 0; nt < 4; nt++)
#pragma unroll
            for (int r = 0; r < 4; r++) acc[mt][nt][r] = 0.f;

    const int nk = K >> 5;

    for (int kt = 0; kt < nk; kt++) {
        {
            const int mtg = arow >> 4, r16 = arow & 15;
            const int g = r16 & 7, hb = r16 >> 3;
            const int seg = (mtg << 1) + (tid & 1);
            const int v = seg & 7;
            float vv[16] = {ra[0].x, ra[0].y, ra[0].z, ra[0].w,
                            ra[1].x, ra[1].y, ra[1].z, ra[1].w,
                            ra[2].x, ra[2].y, ra[2].z, ra[2].w,
                            ra[3].x, ra[3].y, ra[3].z, ra[3].w};
#pragma unroll
            for (int p = 0; p < 8; p++) {
                int t = p & 3, kh = p >> 2;
                int ls = ((g << 2) + t) ^ v;
                As[(((seg << 5) + ls) << 2) + hb + (kh << 1)] =
                    pack_bf2(vv[2 * p], vv[2 * p + 1]);
            }
        }
        if (BT) {
            const int n = tid >> 1;
            const int g = n & 7, ntg = n >> 3;
            const int ks = tid & 1;
            const int segB = (ntg << 1) + ks;
            const int v = ntg & 15;
            float vv[16] = {rb[0].x, rb[0].y, rb[0].z, rb[0].w,
                            rb[1].x, rb[1].y, rb[1].z, rb[1].w,
                            rb[2].x, rb[2].y, rb[2].z, rb[2].w,
                            rb[3].x, rb[3].y, rb[3].z, rb[3].w};
#pragma unroll
            for (int p = 0; p < 8; p++) {
                int t = p & 3, breg = p >> 2;
                int ls = ((g << 2) + t) ^ v;
                Bs[(((segB << 5) + ls) << 1) + breg] =
                    pack_bf2(vv[2 * p], vv[2 * p + 1]);
            }
        } else {
            const int kp = tid >> 4;
            const int cg = tid & 15;
            const int ks = kp >> 3, t = kp & 3, breg = (kp >> 2) & 1;
            const int segB = (cg << 1) + ks;
            const int v = cg & 15;
            float r0[8] = {rb[0].x, rb[0].y, rb[0].z, rb[0].w,
                           rb[1].x, rb[1].y, rb[1].z, rb[1].w};
            float r1[8] = {rb[2].x, rb[2].y, rb[2].z, rb[2].w,
                           rb[3].x, rb[3].y, rb[3].z, rb[3].w};
#pragma unroll
            for (int j = 0; j < 8; j++) {
                int ls = ((j << 2) + t) ^ v;
                Bs[(((segB << 5) + ls) << 1) + breg] = pack_bf2(r0[j], r1[j]);
            }
        }
        __syncthreads();

        if (kt + 1 < nk) {
            const float* Ap2 = Ap + (size_t)(kt + 1) * 32;
#pragma unroll
            for (int u = 0; u < 4; u++) ra[u] = ((const float4*)Ap2)[u];
            if (BT) {
                const float* Bp2 = Bp + (size_t)(kt + 1) * 32;
#pragma unroll
                for (int u = 0; u < 4; u++) rb[u] = ((const float4*)Bp2)[u];
            } else {
                const float* Bp2 = Bp + (size_t)(kt + 1) * 32 * N;
                rb[0] = ((const float4*)Bp2)[0];
                rb[1] = ((const float4*)Bp2)[1];
                rb[2] = ((const float4*)(Bp2 + N))[0];
                rb[3] = ((const float4*)(Bp2 + N))[1];
            }
        }

#pragma unroll
        for (int ks = 0; ks < 2; ks++) {
            uint4 af[4];
            uint2 bf[4];
#pragma unroll
            for (int mt = 0; mt < 4; mt++) {
                int seg = (((wm << 2) + mt) << 1) + ks;
                af[mt] = ((const uint4*)As)[(seg << 5) + (lane ^ (seg & 7))];
            }
#pragma unroll
            for (int nt = 0; nt < 4; nt++) {
                int ntg = (wn << 2) + nt;
                int segB = (ntg << 1) + ks;
                bf[nt] = ((const uint2*)Bs)[(segB << 5) + (lane ^ (ntg & 15))];
            }
#pragma unroll
            for (int mt = 0; mt < 4; mt++)
#pragma unroll
                for (int nt = 0; nt < 4; nt++)
                    mma16(acc[mt][nt], (const uint32_t*)&af[mt],
                          (const uint32_t*)&bf[nt]);
        }
        __syncthreads();
    }

    const int g  = lane >> 2;
    const int t2 = (lane & 3) << 1;
#pragma unroll
    for (int mt = 0; mt < 4; mt++) {
        int row = bm + wm * 64 + mt * 16 + g;
#pragma unroll
        for (int nt = 0; nt < 4; nt++) {
            int col = bn + wn * 32 + nt * 8 + t2;
            float4 r = {acc[mt][nt][0], acc[mt][nt][1],
                        acc[mt][nt][2], acc[mt][nt][3]};
            if (EPI >= 1) {
                float b0 = bias[col], b1 = bias[col + 1];
                r.x += b0; r.y += b1; r.z += b0; r.w += b1;
            }
            if (EPI == 2) {
                r.x = fmaxf(r.x, 0.f); r.y = fmaxf(r.y, 0.f);
                r.z = fmaxf(r.z, 0.f); r.w = fmaxf(r.w, 0.f);
            }
            *(float2*)&C[(size_t)row * N + col]       = make_float2(r.x, r.y);
            *(float2*)&C[(size_t)(row + 8) * N + col] = make_float2(r.z, r.w);
        }
    }
}

// ---------------------------------------------------------------------------
// Fused relative attention. AC and BD score stages now run on tensor cores
// (bf16 mma.m16n8k16, fp32 accumulate); softmax and PV unchanged (fp32).
//
// Per CTA (16 queries, head n, batch b):
//   AC: S[i][j]  = (q_i+bw) . k_j       -> M=16, N=8-per-tile, K=64 MMA
//   BD: T[i][jr] = (q_i+br) . rk_jr     -> same MMA; scattered add at
//       j = jr + (i0+i) - 511 (bijective (jr,i)->(j,i): race-free)
// Fragment mappings identical to the validated GEMM scheme.
// ---------------------------------------------------------------------------
#define ATTN_SP   17
#define ATTN_SMEM ((KLEN_*ATTN_SP + 1024 + 1024 + 4096 + 16) * 4)

__global__ __launch_bounds__(256) void attn_kernel(
    const float* __restrict__ q,  const float* __restrict__ kv,
    const float* __restrict__ rk, const float* __restrict__ bw,
    const float* __restrict__ br, float* __restrict__ vec)
{
    extern __shared__ float sm[];
    float* s    = sm;
    float* qw   = sm + KLEN_ * ATTN_SP;
    float* qr   = qw + 1024;
    float* red  = qr + 1024;
    float* sinv = red + 4096;

    const int itile = blockIdx.x, n = blockIdx.y, b = blockIdx.z;
    const int tid = threadIdx.x;
    const int lane = tid & 31;
    const int w = tid >> 5;
    const int i0 = itile << 4;
    const int cmax = i0 + 528;

    // load 16 query rows (+ biases) into smem
    for (int u = tid; u < 1024; u += 256) {
        int i = u >> 6, d = u & 63;
        float qv = q[((size_t)(b * QLEN_ + i0 + i) << 10) + n * 64 + d];
        qw[u] = qv + bw[n * 64 + d];
        qr[u] = qv + br[n * 64 + d];
    }
    __syncthreads();

    // ---- build A-fragments (qw and qr), 4 k16-steps -----------------------
    const int r0 = lane >> 2;            // fragment row group 0..7
    const int kc = (lane & 3) << 1;      // k-pair base 0,2,4,6
    uint32_t aw[4][4], ar[4][4];
#pragma unroll
    for (int ks = 0; ks < 4; ks++) {
        int d = (ks << 4) + kc;
        aw[ks][0] = pack_bf2(qw[(r0      << 6) + d],     qw[(r0      << 6) + d + 1]);
        aw[ks][1] = pack_bf2(qw[((r0+8)  << 6) + d],     qw[((r0+8)  << 6) + d + 1]);
        aw[ks][2] = pack_bf2(qw[(r0      << 6) + d + 8], qw[(r0      << 6) + d + 9]);
        aw[ks][3] = pack_bf2(qw[((r0+8)  << 6) + d + 8], qw[((r0+8)  << 6) + d + 9]);
        ar[ks][0] = pack_bf2(qr[(r0      << 6) + d],     qr[(r0      << 6) + d + 1]);
        ar[ks][1] = pack_bf2(qr[((r0+8)  << 6) + d],     qr[((r0+8)  << 6) + d + 1]);
        ar[ks][2] = pack_bf2(qr[(r0      << 6) + d + 8], qr[(r0      << 6) + d + 9]);
        ar[ks][3] = pack_bf2(qr[((r0+8)  << 6) + d + 8], qr[((r0+8)  << 6) + d + 9]);
    }

    // ---- AC: S[i][j] over j-tiles of 8 keys --------------------------------
    const int ntiles = cmax >> 3;
    for (int t = w; t < ntiles; t += 8) {
        const int jb = t << 3;
        const float* kbase = kv + ((size_t)(b * KLEN_ + jb + r0) << 11) + n * 64 + kc;
        float c[4] = {0.f, 0.f, 0.f, 0.f};
#pragma unroll
        for (int ks = 0; ks < 4; ks++) {
            float2 lo = *(const float2*)(kbase + (ks << 4));
            float2 hi = *(const float2*)(kbase + (ks << 4) + 8);
            uint32_t bb[2] = {pack_bf2(lo.x, lo.y), pack_bf2(hi.x, hi.y)};
            mma16(c, aw[ks], bb);
        }
        const int jj = jb + kc;
        s[ jj      * ATTN_SP + r0    ] = c[0];
        s[(jj + 1) * ATTN_SP + r0    ] = c[1];
        s[ jj      * ATTN_SP + r0 + 8] = c[2];
        s[(jj + 1) * ATTN_SP + r0 + 8] = c[3];
    }
    __syncthreads();

    // ---- BD: T[i][jr] over all 128 jr-tiles; scatter-add at shifted j ------
    for (int t = w; t < 128; t += 8) {
        const int jrb = t << 3;
        const float* rbase = rk + ((size_t)(jrb + r0) << 10) + n * 64 + kc;
        float c[4] = {0.f, 0.f, 0.f, 0.f};
#pragma unroll
        for (int ks = 0; ks < 4; ks++) {
            float2 lo = *(const float2*)(rbase + (ks << 4));
            float2 hi = *(const float2*)(rbase + (ks << 4) + 8);
            uint32_t bb[2] = {pack_bf2(lo.x, lo.y), pack_bf2(hi.x, hi.y)};
            mma16(c, ar[ks], bb);
        }
        const int jr = jrb + kc;
        const int ja = jr + i0 + r0 - 511;       // i = r0
        const int jb2 = ja + 8;                  // i = r0 + 8
        if (ja     >= 0) s[ ja      * ATTN_SP + r0    ] += c[0];
        if (ja + 1 >= 0) s[(ja + 1) * ATTN_SP + r0    ] += c[1];
        if (jb2    >= 0) s[ jb2     * ATTN_SP + r0 + 8] += c[2];
        if (jb2 + 1>= 0) s[(jb2 + 1)* ATTN_SP + r0 + 8] += c[3];
    }
    __syncthreads();

    // ---- softmax over j in [0, i+513); store unnormalized p, keep 1/sum ----
    {
        for (int i = w; i < 16; i += 8) {
            int count = i0 + i + 513;
            float m = -1e30f;
            for (int j = lane; j < count; j += 32)
                m = fmaxf(m, s[j * ATTN_SP + i]);
#pragma unroll
            for (int o = 16; o; o >>= 1)
                m = fmaxf(m, __shfl_xor_sync(0xffffffffu, m, o));
            float sum = 0.f;
            for (int j = lane; j < count; j += 32) {
                float p = expf((s[j * ATTN_SP + i] - m) * 0.125f);
                s[j * ATTN_SP + i] = p;
                sum += p;
            }
#pragma unroll
            for (int o = 16; o; o >>= 1)
                sum += __shfl_xor_sync(0xffffffffu, sum, o);
            if (lane == 0) sinv[i] = 1.f / sum;
            for (int j = count + lane; j < cmax; j += 32)
                s[j * ATTN_SP + i] = 0.f;
        }
    }
    __syncthreads();

    // ---- vec[i, d] = (sum_j p[i,j] * v[j, d]) * sinv[i] ---------------------
    {
        int d = tid & 63, grp = tid >> 6;
        float acc[16];
#pragma unroll
        for (int i = 0; i < 16; i++) acc[i] = 0.f;
        for (int j = grp; j < cmax; j += 4) {
            float vv = kv[((size_t)(b * KLEN_ + j) << 11) + 1024 + n * 64 + d];
#pragma unroll
            for (int i = 0; i < 16; i++)
                acc[i] += s[j * ATTN_SP + i] * vv;
        }
#pragma unroll
        for (int i = 0; i < 16; i++) red[((grp << 4) + i) * 64 + d] = acc[i];
        __syncthreads();
        if (grp == 0) {
#pragma unroll
            for (int i = 0; i < 16; i++) {
                float rsum = red[i * 64 + d] + red[(16 + i) * 64 + d]
                           + red[(32 + i) * 64 + d] + red[(48 + i) * 64 + d];
                vec[((size_t)(b * QLEN_ + i0 + i) << 10) + n * 64 + d] = rsum * sinv[i];
            }
        }
    }
}

// ---------------------------------------------------------------------------
// x = LayerNorm(x + y) * g + b
// ---------------------------------------------------------------------------
__global__ __launch_bounds__(256) void add_ln_kernel(
    float* __restrict__ x, const float* __restrict__ y,
    const float* __restrict__ g, const float* __restrict__ bb)
{
    int row = blockIdx.x, tid = threadIdx.x;
    float* xr = x + (size_t)row * DMOD;
    const float* yr = y + (size_t)row * DMOD;
    float v[4];
    float s = 0.f, sq = 0.f;
#pragma unroll
    for (int u = 0; u < 4; u++) {
        int idx = tid + (u << 8);
        v[u] = xr[idx] + yr[idx];
        s += v[u]; sq += v[u] * v[u];
    }
#pragma unroll
    for (int o = 16; o; o >>= 1) {
        s  += __shfl_xor_sync(0xffffffffu, s,  o);
        sq += __shfl_xor_sync(0xffffffffu, sq, o);
    }
    __shared__ float ws[8], wq[8];
    if ((tid & 31) == 0) { ws[tid >> 5] = s; wq[tid >> 5] = sq; }
    __syncthreads();
    s = 0.f; sq = 0.f;
#pragma unroll
    for (int u = 0; u < 8; u++) { s += ws[u]; sq += wq[u]; }
    float mu   = s * (1.f / DMOD);
    float var  = sq * (1.f / DMOD) - mu * mu;
    float rstd = rsqrtf(var + 1e-5f);
#pragma unroll
    for (int u = 0; u < 4; u++) {
        int idx = tid + (u << 8);
        xr[idx] = (v[u] - mu) * rstd * g[idx] + bb[idx];
    }
}

// ---------------------------------------------------------------------------
// NLL
// ---------------------------------------------------------------------------
__global__ __launch_bounds__(256) void nll_kernel(
    const float* __restrict__ logits, const int* __restrict__ target,
    float* __restrict__ out)
{
    int row = blockIdx.x, tid = threadIdx.x;
    const float* lr = logits + (size_t)row * VOCAB;

    float m = -1e30f;
    for (int j = tid; j < VOCAB; j += 256) m = fmaxf(m, lr[j]);
#pragma unroll
    for (int o = 16; o; o >>= 1) m = fmaxf(m, __shfl_xor_sync(0xffffffffu, m, o));
    __shared__ float wm[8];
    if ((tid & 31) == 0) wm[tid >> 5] = m;
    __syncthreads();
#pragma unroll
    for (int u = 0; u < 8; u++) m = fmaxf(m, wm[u]);

    float s = 0.f;
    for (int j = tid; j < VOCAB; j += 256) s += expf(lr[j] - m);
#pragma unroll
    for (int o = 16; o; o >>= 1) s += __shfl_xor_sync(0xffffffffu, s, o);
    __shared__ float wsum[8];
    if ((tid & 31) == 0) wsum[tid >> 5] = s;
    __syncthreads();

    if (tid == 0) {
        float tot = 0.f;
#pragma unroll
        for (int u = 0; u < 8; u++) tot += wsum[u];
        out[row] = -(lr[target[row]] - m - logf(tot));
    }
}

// ---------------------------------------------------------------------------
// Orchestration
// ---------------------------------------------------------------------------
extern "C" void kernel_launch(void* const* d_in, const int* in_sizes, int n_in,
                              void* d_out, int out_size)
{
    const int*   data   = (const int*)  d_in[0];
    const int*   target = (const int*)  d_in[1];
    const float* memory = (const float*)d_in[2];
    const float* emb    = (const float*)d_in[3];
    const float* Wq     = (const float*)d_in[4];
    const float* Wkv    = (const float*)d_in[5];
    const float* Wr     = (const float*)d_in[6];
    const float* Wo     = (const float*)d_in[7];
    const float* W1     = (const float*)d_in[8];
    const float* b1     = (const float*)d_in[9];
    const float* W2     = (const float*)d_in[10];
    const float* b2     = (const float*)d_in[11];
    const float* g1     = (const float*)d_in[12];
    const float* be1    = (const float*)d_in[13];
    const float* g2     = (const float*)d_in[14];
    const float* be2    = (const float*)d_in[15];
    const float* bw     = (const float*)d_in[16];
    const float* brr    = (const float*)d_in[17];
    float* out = (float*)d_out;

    float *x, *xc, *qb, *kvb, *rkb, *pos, *vecb, *tmp, *ffh, *lg;
    cudaGetSymbolAddress((void**)&x,    g_x);
    cudaGetSymbolAddress((void**)&xc,   g_xcat);
    cudaGetSymbolAddress((void**)&qb,   g_q);
    cudaGetSymbolAddress((void**)&kvb,  g_kv);
    cudaGetSymbolAddress((void**)&rkb,  g_rk);
    cudaGetSymbolAddress((void**)&pos,  g_pos);
    cudaGetSymbolAddress((void**)&vecb, g_vec);
    cudaGetSymbolAddress((void**)&tmp,  g_tmp);
    cudaGetSymbolAddress((void**)&ffh,  g_ffh);
    cudaGetSymbolAddress((void**)&lg,   g_lgt);

    cudaFuncSetAttribute(attn_kernel,
                         cudaFuncAttributeMaxDynamicSharedMemorySize, ATTN_SMEM);

    embed_kernel <<<NROWS, 256>>>(data, emb, x);
    posemb_kernel<<<KLEN_, 512>>>(pos);

    for (int l = 0; l < NLYR; l++) {
        const float* memL = memory + (size_t)l * BSZ_ * QLEN_ * DMOD;

        concat_kernel<<<NCROWS, 256>>>(memL, x, xc);

        // q = x @ Wq[l]                          [2048,1024] x [1024,1024]
        gemm_bf16<0, false><<<dim3(8, 16), 256>>>(
            x, Wq + (size_t)l * DMOD * DMOD, nullptr, qb, NROWS, DMOD, DMOD);
        // kv = xcat @ Wkv[l]                     [4096,1024] x [1024,2048]
        gemm_bf16<0, false><<<dim3(16, 32), 256>>>(
            xc, Wkv + (size_t)l * DMOD * 2 * DMOD, nullptr, kvb, NCROWS, 2 * DMOD, DMOD);
        // rk = pos @ Wr[l]                       [1024,1024] x [1024,1024]
        gemm_bf16<0, false><<<dim3(8, 8), 256>>>(
            pos, Wr + (size_t)l * DMOD * DMOD, nullptr, rkb, KLEN_, DMOD, DMOD);

        attn_kernel<<<dim3(32, 16, 4), 256, ATTN_SMEM>>>(qb, kvb, rkb, bw, brr, vecb);

        // attn_out = vec @ Wo[l]
        gemm_bf16<0, false><<<dim3(8, 16), 256>>>(
            vecb, Wo + (size_t)l * DMOD * DMOD, nullptr, tmp, NROWS, DMOD, DMOD);
        add_ln_kernel<<<NROWS, 256>>>(x, tmp, g1 + l * DMOD, be1 + l * DMOD);

        // ff = relu(x @ W1 + b1) @ W2 + b2
        gemm_bf16<2, false><<<dim3(32, 16), 256>>>(
            x, W1 + (size_t)l * DMOD * DINNER, b1 + (size_t)l * DINNER,
            ffh, NROWS, DINNER, DMOD);
        gemm_bf16<1, false><<<dim3(8, 16), 256>>>(
            ffh, W2 + (size_t)l * DINNER * DMOD, b2 + (size_t)l * DMOD,
            tmp, NROWS, DMOD, DINNER);
        add_ln_kernel<<<NROWS, 256>>>(x, tmp, g2 + l * DMOD, be2 + l * DMOD);
    }

    // logits = x @ emb^T   [2048,1024] x [32000,1024]^T
    gemm_bf16<0, true><<<dim3(VOCAB / 128, 16), 256>>>(
        x, emb, nullptr, lg, NROWS, VOCAB, DMOD);

    nll_kernel<<<NROWS, 256>>>(lg, target, out);
}